// round 1
// baseline (speedup 1.0000x reference)
#include <cuda_runtime.h>
#include <cuda_bf16.h>
#include <math.h>

// ---------------------------------------------------------------------------
// Problem constants
// ---------------------------------------------------------------------------
constexpr int BATCH  = 4;
constexpr int SEQ    = 2048;
constexpr int DMODEL = 512;
constexpr int NH     = 8;
constexpr int HD     = 64;     // dk = dv = 64
constexpr int FFI    = 2048;
constexpr int MROWS  = BATCH * SEQ;   // 8192

// ---------------------------------------------------------------------------
// Device scratch (static __device__ arrays: allocation-free per harness rules)
// ---------------------------------------------------------------------------
__device__ float g_Wqkv[DMODEL * 3 * DMODEL];          // [d][1536] repacked
__device__ float g_q[BATCH * NH * SEQ * HD];           // [b][h][t][k]
__device__ float g_k[BATCH * NH * SEQ * HD];
__device__ float g_v[BATCH * NH * SEQ * HD];
__device__ float g_att[MROWS * DMODEL];                // raw-reshape layout
__device__ float g_out[MROWS * DMODEL];
__device__ float g_h[MROWS * FFI];

// ---------------------------------------------------------------------------
// Repack Wq|Wk|Wv (H, DMODEL, HD) -> row-major [DMODEL][3*DMODEL]
// column c in [0,512): q head h=c/64 dim c%64; [512,1024): k; [1024,1536): v
// ---------------------------------------------------------------------------
__global__ void repack_qkv(const float* __restrict__ Wq,
                           const float* __restrict__ Wk,
                           const float* __restrict__ Wv) {
    int i = blockIdx.x * 256 + threadIdx.x;
    if (i >= DMODEL * DMODEL) return;
    int d = i / DMODEL, c = i % DMODEL;
    int h = c >> 6, kk = c & 63;
    int src = (h * DMODEL + d) * HD + kk;
    g_Wqkv[d * 1536 + c]        = Wq[src];
    g_Wqkv[d * 1536 + 512 + c]  = Wk[src];
    g_Wqkv[d * 1536 + 1024 + c] = Wv[src];
}

// ---------------------------------------------------------------------------
// SGEMM: C[M,N] = A[M,K] @ B[K,N]   (all row-major, M%128==0, N%128==0, K%8==0)
// 128x128 tile, BK=8, 256 threads, 8x8 per-thread register tile.
// EPI: 0 = plain, 1 = +bias, 2 = +bias+ReLU, 3 = scatter into g_q/g_k/g_v
// ---------------------------------------------------------------------------
template <int EPI>
__global__ __launch_bounds__(256)
void sgemm128(const float* __restrict__ A, const float* __restrict__ Bm,
              float* __restrict__ C, const float* __restrict__ bias,
              int M, int N, int K) {
    constexpr int BM = 128, BN = 128, BK = 8, TM = 8, TN = 8;
    __shared__ float As[BK][BM];
    __shared__ float Bs[BK][BN];

    const int tid = threadIdx.x;
    const int tx = tid & 15;      // 16 cols of threads
    const int ty = tid >> 4;      // 16 rows of threads
    const int rowBase = blockIdx.y * BM;
    const int colBase = blockIdx.x * BN;

    float acc[TM][TN];
#pragma unroll
    for (int i = 0; i < TM; i++)
#pragma unroll
        for (int j = 0; j < TN; j++) acc[i][j] = 0.f;

    const int aRow = tid >> 1, aCol = (tid & 1) * 4;   // 128 rows x 8 k
    const int bRow = tid >> 5, bCol = (tid & 31) * 4;  // 8 k x 128 cols

    const float* Aptr = A + (size_t)(rowBase + aRow) * K + aCol;
    const float* Bptr = Bm + (size_t)bRow * N + colBase + bCol;

    for (int k0 = 0; k0 < K; k0 += BK) {
        float4 av = *(const float4*)(Aptr + k0);
        float4 bv = *(const float4*)(Bptr + (size_t)k0 * N);
        As[aCol + 0][aRow] = av.x;
        As[aCol + 1][aRow] = av.y;
        As[aCol + 2][aRow] = av.z;
        As[aCol + 3][aRow] = av.w;
        *(float4*)&Bs[bRow][bCol] = bv;
        __syncthreads();
#pragma unroll
        for (int kk = 0; kk < BK; kk++) {
            float a[TM], b[TN];
#pragma unroll
            for (int i = 0; i < TM; i++) a[i] = As[kk][ty * TM + i];
#pragma unroll
            for (int j = 0; j < TN; j++) b[j] = Bs[kk][tx * TN + j];
#pragma unroll
            for (int i = 0; i < TM; i++)
#pragma unroll
                for (int j = 0; j < TN; j++) acc[i][j] += a[i] * b[j];
        }
        __syncthreads();
    }

    if (EPI == 3) {
        // scatter QKV: row m -> (b, t); col c -> (which, h, kk)
#pragma unroll
        for (int i = 0; i < TM; i++) {
            int m = rowBase + ty * TM + i;
            int bb = m >> 11;          // /SEQ
            int t  = m & 2047;
#pragma unroll
            for (int j = 0; j < TN; j++) {
                int c = colBase + tx * TN + j;
                int which = c >> 9;
                int c2 = c & 511;
                int h = c2 >> 6, kk2 = c2 & 63;
                float* dst = (which == 0) ? g_q : (which == 1) ? g_k : g_v;
                dst[(((size_t)(bb * NH + h)) * SEQ + t) * HD + kk2] = acc[i][j];
            }
        }
    } else {
#pragma unroll
        for (int i = 0; i < TM; i++) {
            size_t row = rowBase + ty * TM + i;
#pragma unroll
            for (int j4 = 0; j4 < TN; j4 += 4) {
                float4 r;
                float* pr = &r.x;
#pragma unroll
                for (int j = 0; j < 4; j++) {
                    float vv = acc[i][j4 + j];
                    if (EPI >= 1) vv += bias[colBase + tx * TN + j4 + j];
                    if (EPI == 2) vv = fmaxf(vv, 0.f);
                    pr[j] = vv;
                }
                *(float4*)&C[row * N + colBase + tx * TN + j4] = r;
            }
        }
    }
}

// ---------------------------------------------------------------------------
// Flash attention: per (b,h), 64-query tiles; online softmax; 256 threads,
// warp w owns query rows w*8..w*8+7, lane owns value/key columns {lane,lane+32}.
// K tile stored transposed with XOR swizzle (conflict-free read+write);
// its buffer is reused for the P tile after a barrier.
// Output written directly in the reference's raw-reshape layout:
//   att[(b*SEQ + h*256 + t/8)*512 + (t%8)*64 + v]
// ---------------------------------------------------------------------------
__global__ __launch_bounds__(256)
void flash_attn() {
    constexpr int BM = 64, BN = 64;
    const int bh = blockIdx.y;
    const int b = bh >> 3, h = bh & 7;
    const int q0 = blockIdx.x * BM;
    const float* Q  = g_q + (size_t)bh * SEQ * HD;
    const float* Kp = g_k + (size_t)bh * SEQ * HD;
    const float* Vp = g_v + (size_t)bh * SEQ * HD;

    __shared__ float Qs[BM][HD];     // 16 KB
    __shared__ float KtPs[HD][BN];   // 16 KB: K^T (swizzled), then P
    __shared__ float Vs[BN][HD];     // 16 KB

    const int tid = threadIdx.x, lane = tid & 31, w = tid >> 5;

    // load Q tile (coalesced, float4)
#pragma unroll
    for (int it = 0; it < 4; it++) {
        int off4 = tid + it * 256;           // 1024 float4s
        int r = off4 >> 4, c = (off4 & 15) * 4;
        *(float4*)&Qs[r][c] = *(const float4*)&Q[(size_t)(q0 + r) * HD + c];
    }

    float mrow[8], lrow[8], acc0[8], acc1[8];
#pragma unroll
    for (int r = 0; r < 8; r++) {
        mrow[r] = -1e30f; lrow[r] = 0.f; acc0[r] = 0.f; acc1[r] = 0.f;
    }
    __syncthreads();

    for (int s0 = 0; s0 < SEQ; s0 += BN) {
        __syncthreads();   // previous iteration's P/V reads complete
        // load K (transposed + swizzled) and V
#pragma unroll
        for (int it = 0; it < 4; it++) {
            int off4 = tid + it * 256;
            int s = off4 >> 4, c = (off4 & 15) * 4;   // key row s, k-dim c..c+3
            float4 kv = *(const float4*)&Kp[(size_t)(s0 + s) * HD + c];
            const float* pk = &kv.x;
#pragma unroll
            for (int i = 0; i < 4; i++)
                KtPs[c + i][s ^ ((c + i) & 31)] = pk[i];
            *(float4*)&Vs[s][c] = *(const float4*)&Vp[(size_t)(s0 + s) * HD + c];
        }
        __syncthreads();

        // scores: sc[r][0] = q_row . K[lane], sc[r][1] = q_row . K[lane+32]
        float sc[8][2];
#pragma unroll
        for (int r = 0; r < 8; r++) { sc[r][0] = 0.f; sc[r][1] = 0.f; }
#pragma unroll 4
        for (int kk = 0; kk < HD; kk++) {
            int cp = lane ^ (kk & 31);
            float k0v = KtPs[kk][cp];
            float k1v = KtPs[kk][cp + 32];
#pragma unroll
            for (int r = 0; r < 8; r++) {
                float qv = Qs[w * 8 + r][kk];
                sc[r][0] += qv * k0v;
                sc[r][1] += qv * k1v;
            }
        }
        constexpr float scale = 0.125f;   // 1/sqrt(64)

        // online softmax (register state per warp-row)
        float p0s[8], p1s[8];
#pragma unroll
        for (int r = 0; r < 8; r++) {
            float s_0 = sc[r][0] * scale, s_1 = sc[r][1] * scale;
            float mx = fmaxf(s_0, s_1);
#pragma unroll
            for (int o = 16; o; o >>= 1)
                mx = fmaxf(mx, __shfl_xor_sync(0xffffffffu, mx, o));
            float mnew = fmaxf(mrow[r], mx);
            float alpha = __expf(mrow[r] - mnew);
            float p0 = __expf(s_0 - mnew);
            float p1 = __expf(s_1 - mnew);
            float rs = p0 + p1;
#pragma unroll
            for (int o = 16; o; o >>= 1)
                rs += __shfl_xor_sync(0xffffffffu, rs, o);
            lrow[r] = lrow[r] * alpha + rs;
            mrow[r] = mnew;
            acc0[r] *= alpha;
            acc1[r] *= alpha;
            p0s[r] = p0; p1s[r] = p1;
        }

        __syncthreads();   // everyone done reading K^T before we overwrite with P
#pragma unroll
        for (int r = 0; r < 8; r++) {
            KtPs[w * 8 + r][lane]      = p0s[r];
            KtPs[w * 8 + r][lane + 32] = p1s[r];
        }
        __syncwarp();

        // O += P @ V  (each warp reads only its own P rows)
#pragma unroll 4
        for (int ss = 0; ss < BN; ss++) {
            float v0 = Vs[ss][lane];
            float v1 = Vs[ss][lane + 32];
#pragma unroll
            for (int r = 0; r < 8; r++) {
                float p = KtPs[w * 8 + r][ss];
                acc0[r] += p * v0;
                acc1[r] += p * v1;
            }
        }
    }

    // write output in the raw-reshape layout
#pragma unroll
    for (int r = 0; r < 8; r++) {
        int t = q0 + w * 8 + r;
        float inv = 1.f / lrow[r];
        size_t row2 = (size_t)b * SEQ + h * 256 + (t >> 3);
        size_t base = row2 * DMODEL + (t & 7) * 64;
        g_att[base + lane]      = acc0[r] * inv;
        g_att[base + lane + 32] = acc1[r] * inv;
    }
}

// ---------------------------------------------------------------------------
// Launch
// ---------------------------------------------------------------------------
extern "C" void kernel_launch(void* const* d_in, const int* in_sizes, int n_in,
                              void* d_out, int out_size) {
    const float* x  = (const float*)d_in[0];
    const float* Wq = (const float*)d_in[1];
    const float* Wk = (const float*)d_in[2];
    const float* Wv = (const float*)d_in[3];
    const float* Wo = (const float*)d_in[4];
    const float* W1 = (const float*)d_in[5];
    const float* b1 = (const float*)d_in[6];
    const float* W2 = (const float*)d_in[7];
    const float* b2 = (const float*)d_in[8];
    float* y = (float*)d_out;

    float *p_wqkv, *p_att, *p_out, *p_h;
    cudaGetSymbolAddress((void**)&p_wqkv, g_Wqkv);
    cudaGetSymbolAddress((void**)&p_att,  g_att);
    cudaGetSymbolAddress((void**)&p_out,  g_out);
    cudaGetSymbolAddress((void**)&p_h,    g_h);

    // 1. repack QKV weights
    repack_qkv<<<(DMODEL * DMODEL + 255) / 256, 256>>>(Wq, Wk, Wv);

    // 2. fused QKV projection: [8192,512] @ [512,1536] -> scatter q,k,v
    sgemm128<3><<<dim3(1536 / 128, MROWS / 128), 256>>>(
        x, p_wqkv, nullptr, nullptr, MROWS, 1536, DMODEL);

    // 3. flash attention -> g_att (raw-reshape layout)
    flash_attn<<<dim3(SEQ / 64, BATCH * NH), 256>>>();

    // 4. output projection: att @ Wo -> g_out
    sgemm128<0><<<dim3(DMODEL / 128, MROWS / 128), 256>>>(
        p_att, Wo, p_out, nullptr, MROWS, DMODEL, DMODEL);

    // 5. FFN1: relu(out @ W1 + b1) -> g_h
    sgemm128<2><<<dim3(FFI / 128, MROWS / 128), 256>>>(
        p_out, W1, p_h, b1, MROWS, FFI, DMODEL);

    // 6. FFN2: h @ W2 + b2 -> d_out
    sgemm128<1><<<dim3(DMODEL / 128, MROWS / 128), 256>>>(
        p_h, W2, y, b2, MROWS, DMODEL, FFI);
}

// round 3
// speedup vs baseline: 1.6478x; 1.6478x over previous
#include <cuda_runtime.h>
#include <cuda_bf16.h>
#include <math.h>
#include <stdint.h>

// ---------------------------------------------------------------------------
// Problem constants
// ---------------------------------------------------------------------------
constexpr int BATCH  = 4;
constexpr int SEQ    = 2048;
constexpr int DMODEL = 512;
constexpr int NH     = 8;
constexpr int HD     = 64;
constexpr int FFI    = 2048;
constexpr int MROWS  = BATCH * SEQ;   // 8192

// ---------------------------------------------------------------------------
// Baseline-PTX helpers (NO arch-"a" features: mma.sync/ldmatrix/cp.async only)
// ---------------------------------------------------------------------------
__device__ __forceinline__ uint32_t smem_u32(const void* p) {
    uint32_t a;
    asm("{ .reg .u64 t; cvta.to.shared.u64 t, %1; cvt.u32.u64 %0, t; }" : "=r"(a) : "l"(p));
    return a;
}
#define CP_ASYNC16(dst, src) \
    asm volatile("cp.async.cg.shared.global [%0], [%1], 16;" :: "r"(dst), "l"(src))
#define CP_COMMIT() asm volatile("cp.async.commit_group;" ::: "memory")
#define CP_WAIT(n)  asm volatile("cp.async.wait_group %0;" :: "n"(n) : "memory")

#define LDSM4(r0, r1, r2, r3, addr) \
    asm volatile("ldmatrix.sync.aligned.m8n8.x4.shared.b16 {%0,%1,%2,%3}, [%4];" \
        : "=r"(r0), "=r"(r1), "=r"(r2), "=r"(r3) : "r"(addr))

#define MMA16816(c, a, b0, b1) \
    asm volatile("mma.sync.aligned.m16n8k16.row.col.f32.bf16.bf16.f32 " \
        "{%0,%1,%2,%3}, {%4,%5,%6,%7}, {%8,%9}, {%0,%1,%2,%3};" \
        : "+f"((c)[0]), "+f"((c)[1]), "+f"((c)[2]), "+f"((c)[3]) \
        : "r"((a)[0]), "r"((a)[1]), "r"((a)[2]), "r"((a)[3]), "r"(b0), "r"(b1))

// ---------------------------------------------------------------------------
// Device scratch: A' = [hi | lo | hi], B' = [hi | hi | lo] along K (3x K)
// ---------------------------------------------------------------------------
#define AL __align__(16)
__device__ AL __nv_bfloat16 g_xp[MROWS * 3 * DMODEL];          // x'      [8192,1536]
__device__ AL __nv_bfloat16 g_qkvWp[1536 * 3 * DMODEL];        // B' qkv  [1536,1536]
__device__ AL float g_q[BATCH * NH * SEQ * HD];
__device__ AL float g_k[BATCH * NH * SEQ * HD];
__device__ AL float g_v[BATCH * NH * SEQ * HD];
__device__ AL __nv_bfloat16 g_attp[MROWS * 3 * DMODEL];        // att'    [8192,1536]
__device__ AL __nv_bfloat16 g_WoTp[DMODEL * 3 * DMODEL];       // B' Wo   [512,1536]
__device__ AL __nv_bfloat16 g_outp[MROWS * 3 * DMODEL];        // out'    [8192,1536]
__device__ AL __nv_bfloat16 g_W1Tp[FFI * 3 * DMODEL];          // B' W1   [2048,1536]
__device__ AL __nv_bfloat16 g_hp[MROWS * 3 * FFI];             // h'      [8192,6144]
__device__ AL __nv_bfloat16 g_W2Tp[DMODEL * 3 * FFI];          // B' W2   [512,6144]

__device__ __forceinline__ void split2(float v, __nv_bfloat16& h, __nv_bfloat16& l) {
    h = __float2bfloat16_rn(v);
    l = __float2bfloat16_rn(v - __bfloat162float(h));
}

// ---------------------------------------------------------------------------
// Prep kernels
// ---------------------------------------------------------------------------
// x [M,K] fp32 -> A' [M,3K] = [hi | lo | hi]
__global__ void split3_rows(const float* __restrict__ in, __nv_bfloat16* __restrict__ out,
                            int M, int K) {
    int i = blockIdx.x * 256 + threadIdx.x;
    if (i >= M * K) return;
    int m = i / K, k = i - m * K;
    __nv_bfloat16 h, l; split2(in[i], h, l);
    size_t base = (size_t)m * 3 * K;
    out[base + k] = h; out[base + K + k] = l; out[base + 2 * K + k] = h;
}

// W [Kd,Nd] fp32 -> B' [Nd,3Kd] = [hi | hi | lo]
__global__ void transpose_split3(const float* __restrict__ W, __nv_bfloat16* __restrict__ out,
                                 int Kd, int Nd) {
    int i = blockIdx.x * 256 + threadIdx.x;
    if (i >= Nd * Kd) return;
    int n = i / Kd, k = i - n * Kd;
    __nv_bfloat16 h, l; split2(W[(size_t)k * Nd + n], h, l);
    size_t base = (size_t)n * 3 * Kd;
    out[base + k] = h; out[base + Kd + k] = h; out[base + 2 * Kd + k] = l;
}

// Wq|Wk|Wv (H, DMODEL, HD) -> B' qkv [1536][1536]
__global__ void prep_qkvW(const float* __restrict__ Wq, const float* __restrict__ Wk,
                          const float* __restrict__ Wv) {
    int i = blockIdx.x * 256 + threadIdx.x;
    if (i >= 1536 * DMODEL) return;
    int n = i >> 9, k = i & 511;
    int which = n >> 9, h = (n >> 6) & 7, kk = n & 63;
    const float* W = which == 0 ? Wq : which == 1 ? Wk : Wv;
    __nv_bfloat16 hh, ll; split2(W[((size_t)h * DMODEL + k) * HD + kk], hh, ll);
    size_t base = (size_t)n * 1536;
    g_qkvWp[base + k] = hh; g_qkvWp[base + 512 + k] = hh; g_qkvWp[base + 1024 + k] = ll;
}

// ---------------------------------------------------------------------------
// bf16 mma.sync GEMM: C[M,N] = A'[M,Kp] @ B'[N,Kp]^T, fp32 accum.
// 128x128 CTA tile, BK=64, 3-stage cp.async ring, 8 warps (warp tile 32x64).
// EPI: 0 = QKV scatter fp32, 1 = triple-split, 2 = bias+relu+triple-split,
//      3 = bias + fp32 out
// ---------------------------------------------------------------------------
constexpr int STAGE_B = 32768;               // A 16KB + B 16KB
constexpr int GEMM_SMEM = 3 * STAGE_B;       // 96 KB

template <int EPI>
__global__ __launch_bounds__(256, 2)
void mma_gemm(const __nv_bfloat16* __restrict__ A, const __nv_bfloat16* __restrict__ B,
              const float* __restrict__ bias, float* __restrict__ outF,
              __nv_bfloat16* __restrict__ outB, int N, int Kp) {
    extern __shared__ char smdyn[];
    const uint32_t sb = smem_u32(smdyn);
    const int tid = threadIdx.x, lane = tid & 31, wid = tid >> 5;
    const int wm = wid & 3, wn = wid >> 2;             // 4 x 2 warp grid
    const int rowBase = blockIdx.y * 128, colBase = blockIdx.x * 128;
    const int chunks = Kp >> 6;

    float C[2][8][4];
#pragma unroll
    for (int a = 0; a < 2; a++)
#pragma unroll
        for (int b = 0; b < 8; b++)
#pragma unroll
            for (int c = 0; c < 4; c++) C[a][b][c] = 0.f;

    // per-thread load slots: 4 x (A chunk + B chunk)
    const int lr = (tid * 4) >> 3;            // not used; keep simple per-i mapping
    (void)lr;

    auto issue = [&](int cchunk) {
        int s = cchunk % 3;
        uint32_t stA = sb + s * STAGE_B, stB = stA + 16384;
        const char* Ag = (const char*)(A + (size_t)rowBase * Kp + cchunk * 64);
        const char* Bg = (const char*)(B + (size_t)colBase * Kp + cchunk * 64);
#pragma unroll
        for (int i = 0; i < 4; i++) {
            int id = tid + i * 256;           // 1024 chunks per operand
            int r = id >> 3, ch = id & 7;
            uint32_t off = (uint32_t)(r * 8 + (ch ^ (r & 7))) * 16;
            CP_ASYNC16(stA + off, Ag + (size_t)r * Kp * 2 + ch * 16);
            CP_ASYNC16(stB + off, Bg + (size_t)r * Kp * 2 + ch * 16);
        }
        CP_COMMIT();
    };

    issue(0);
    if (chunks > 1) issue(1);

    // ldmatrix lane constants
    const int laneA_row = lane & 15;                       // + m0
    const int laneA_ks  = lane >> 4;                       // 0/1 -> +8 in k
    const int laneB_row = (lane & 7) + ((lane >> 4) << 3); // + n0
    const int laneB_ks  = (lane >> 3) & 1;

    for (int c = 0; c < chunks; c++) {
        CP_WAIT(1);
        __syncthreads();
        if (c + 2 < chunks) issue(c + 2);

        int s = c % 3;
        uint32_t stA = sb + s * STAGE_B, stB = stA + 16384;

#pragma unroll
        for (int ks = 0; ks < 4; ks++) {
            uint32_t a[2][4];
#pragma unroll
            for (int mt = 0; mt < 2; mt++) {
                int rowA = wm * 32 + mt * 16 + laneA_row;
                int chA = ks * 2 + laneA_ks;
                uint32_t ad = stA + (uint32_t)(rowA * 8 + (chA ^ (rowA & 7))) * 16;
                LDSM4(a[mt][0], a[mt][1], a[mt][2], a[mt][3], ad);
            }
#pragma unroll
            for (int np = 0; np < 4; np++) {
                int rowB = wn * 64 + np * 16 + laneB_row;
                int chB = ks * 2 + laneB_ks;
                uint32_t bd = stB + (uint32_t)(rowB * 8 + (chB ^ (rowB & 7))) * 16;
                uint32_t b0, b1, b2, b3;
                LDSM4(b0, b1, b2, b3, bd);
#pragma unroll
                for (int mt = 0; mt < 2; mt++) {
                    MMA16816(C[mt][np * 2 + 0], a[mt], b0, b1);
                    MMA16816(C[mt][np * 2 + 1], a[mt], b2, b3);
                }
            }
        }
    }

    // ---------------- epilogue (register -> gmem) ----------------
#pragma unroll
    for (int mt = 0; mt < 2; mt++) {
#pragma unroll
        for (int half = 0; half < 2; half++) {
            int m = rowBase + wm * 32 + mt * 16 + (lane >> 2) + half * 8;
#pragma unroll
            for (int nt = 0; nt < 8; nt++) {
                int n = colBase + wn * 64 + nt * 8 + (lane & 3) * 2;
                float v0 = C[mt][nt][half * 2 + 0];
                float v1 = C[mt][nt][half * 2 + 1];
                if (EPI == 0) {
                    // scatter q/k/v fp32
                    int b = m >> 11, t = m & 2047;
                    int which = n >> 9, h = (n >> 6) & 7, kk = n & 63;
                    float* dst = which == 0 ? g_q : which == 1 ? g_k : g_v;
                    float2 v = make_float2(v0, v1);
                    *(float2*)&dst[(((size_t)(b * NH + h)) * SEQ + t) * HD + kk] = v;
                } else if (EPI == 3) {
                    float2 v = make_float2(v0 + bias[n], v1 + bias[n + 1]);
                    *(float2*)&outF[(size_t)m * N + n] = v;
                } else {
                    if (EPI == 2) {
                        v0 = fmaxf(v0 + bias[n], 0.f);
                        v1 = fmaxf(v1 + bias[n + 1], 0.f);
                    }
                    __nv_bfloat16 h0, l0, h1, l1;
                    split2(v0, h0, l0);
                    split2(v1, h1, l1);
                    union { __nv_bfloat16 b[2]; uint32_t u; } ph, pl;
                    ph.b[0] = h0; ph.b[1] = h1;
                    pl.b[0] = l0; pl.b[1] = l1;
                    size_t base = (size_t)m * (3 * N) + n;
                    *(uint32_t*)&outB[base]         = ph.u;
                    *(uint32_t*)&outB[base + N]     = pl.u;
                    *(uint32_t*)&outB[base + 2 * N] = ph.u;
                }
            }
        }
    }
}

// ---------------------------------------------------------------------------
// Flash attention (SIMT fp32) -> att' triple layout (raw-reshape rows)
// ---------------------------------------------------------------------------
__global__ __launch_bounds__(256)
void flash_attn() {
    constexpr int BM = 64, BN = 64;
    const int bh = blockIdx.y;
    const int b = bh >> 3, h = bh & 7;
    const int q0 = blockIdx.x * BM;
    const float* Q  = g_q + (size_t)bh * SEQ * HD;
    const float* Kp = g_k + (size_t)bh * SEQ * HD;
    const float* Vp = g_v + (size_t)bh * SEQ * HD;

    __shared__ float Qs[BM][HD];
    __shared__ float KtPs[HD][BN];
    __shared__ float Vs[BN][HD];

    const int tid = threadIdx.x, lane = tid & 31, w = tid >> 5;

#pragma unroll
    for (int it = 0; it < 4; it++) {
        int off4 = tid + it * 256;
        int r = off4 >> 4, c = (off4 & 15) * 4;
        *(float4*)&Qs[r][c] = *(const float4*)&Q[(size_t)(q0 + r) * HD + c];
    }

    float mrow[8], lrow[8], acc0[8], acc1[8];
#pragma unroll
    for (int r = 0; r < 8; r++) { mrow[r] = -1e30f; lrow[r] = 0.f; acc0[r] = 0.f; acc1[r] = 0.f; }
    __syncthreads();

    for (int s0 = 0; s0 < SEQ; s0 += BN) {
        __syncthreads();
#pragma unroll
        for (int it = 0; it < 4; it++) {
            int off4 = tid + it * 256;
            int s = off4 >> 4, c = (off4 & 15) * 4;
            float4 kv = *(const float4*)&Kp[(size_t)(s0 + s) * HD + c];
            const float* pk = &kv.x;
#pragma unroll
            for (int i = 0; i < 4; i++)
                KtPs[c + i][s ^ ((c + i) & 31)] = pk[i];
            *(float4*)&Vs[s][c] = *(const float4*)&Vp[(size_t)(s0 + s) * HD + c];
        }
        __syncthreads();

        float sc[8][2];
#pragma unroll
        for (int r = 0; r < 8; r++) { sc[r][0] = 0.f; sc[r][1] = 0.f; }
#pragma unroll 4
        for (int kk = 0; kk < HD; kk++) {
            int cp = lane ^ (kk & 31);
            float k0v = KtPs[kk][cp];
            float k1v = KtPs[kk][cp + 32];
#pragma unroll
            for (int r = 0; r < 8; r++) {
                float qv = Qs[w * 8 + r][kk];
                sc[r][0] += qv * k0v;
                sc[r][1] += qv * k1v;
            }
        }
        constexpr float scale = 0.125f;

        float p0s[8], p1s[8];
#pragma unroll
        for (int r = 0; r < 8; r++) {
            float s_0 = sc[r][0] * scale, s_1 = sc[r][1] * scale;
            float mx = fmaxf(s_0, s_1);
#pragma unroll
            for (int o = 16; o; o >>= 1)
                mx = fmaxf(mx, __shfl_xor_sync(0xffffffffu, mx, o));
            float mnew = fmaxf(mrow[r], mx);
            float alpha = __expf(mrow[r] - mnew);
            float p0 = __expf(s_0 - mnew);
            float p1 = __expf(s_1 - mnew);
            float rs = p0 + p1;
#pragma unroll
            for (int o = 16; o; o >>= 1)
                rs += __shfl_xor_sync(0xffffffffu, rs, o);
            lrow[r] = lrow[r] * alpha + rs;
            mrow[r] = mnew;
            acc0[r] *= alpha;
            acc1[r] *= alpha;
            p0s[r] = p0; p1s[r] = p1;
        }

        __syncthreads();
#pragma unroll
        for (int r = 0; r < 8; r++) {
            KtPs[w * 8 + r][lane]      = p0s[r];
            KtPs[w * 8 + r][lane + 32] = p1s[r];
        }
        __syncwarp();

#pragma unroll 4
        for (int ss = 0; ss < BN; ss++) {
            float v0 = Vs[ss][lane];
            float v1 = Vs[ss][lane + 32];
#pragma unroll
            for (int r = 0; r < 8; r++) {
                float p = KtPs[w * 8 + r][ss];
                acc0[r] += p * v0;
                acc1[r] += p * v1;
            }
        }
    }

#pragma unroll
    for (int r = 0; r < 8; r++) {
        int t = q0 + w * 8 + r;
        float inv = 1.f / lrow[r];
        size_t row2 = (size_t)b * SEQ + h * 256 + (t >> 3);
        size_t base = row2 * 1536 + (t & 7) * 64;
        float v0 = acc0[r] * inv, v1 = acc1[r] * inv;
        __nv_bfloat16 h0, l0, h1, l1;
        split2(v0, h0, l0);
        split2(v1, h1, l1);
        g_attp[base + lane]              = h0;
        g_attp[base + 512 + lane]        = l0;
        g_attp[base + 1024 + lane]       = h0;
        g_attp[base + lane + 32]         = h1;
        g_attp[base + 512 + lane + 32]   = l1;
        g_attp[base + 1024 + lane + 32]  = h1;
    }
}

// ---------------------------------------------------------------------------
// Launch
// ---------------------------------------------------------------------------
extern "C" void kernel_launch(void* const* d_in, const int* in_sizes, int n_in,
                              void* d_out, int out_size) {
    const float* x  = (const float*)d_in[0];
    const float* Wq = (const float*)d_in[1];
    const float* Wk = (const float*)d_in[2];
    const float* Wv = (const float*)d_in[3];
    const float* Wo = (const float*)d_in[4];
    const float* W1 = (const float*)d_in[5];
    const float* b1 = (const float*)d_in[6];
    const float* W2 = (const float*)d_in[7];
    const float* b2 = (const float*)d_in[8];
    float* y = (float*)d_out;

    void *xp, *qwp, *atp, *wop, *outp, *w1p, *hp, *w2p;
    cudaGetSymbolAddress(&xp,  g_xp);
    cudaGetSymbolAddress(&qwp, g_qkvWp);
    cudaGetSymbolAddress(&atp, g_attp);
    cudaGetSymbolAddress(&wop, g_WoTp);
    cudaGetSymbolAddress(&outp, g_outp);
    cudaGetSymbolAddress(&w1p, g_W1Tp);
    cudaGetSymbolAddress(&hp,  g_hp);
    cudaGetSymbolAddress(&w2p, g_W2Tp);

    cudaFuncSetAttribute(mma_gemm<0>, cudaFuncAttributeMaxDynamicSharedMemorySize, GEMM_SMEM);
    cudaFuncSetAttribute(mma_gemm<1>, cudaFuncAttributeMaxDynamicSharedMemorySize, GEMM_SMEM);
    cudaFuncSetAttribute(mma_gemm<2>, cudaFuncAttributeMaxDynamicSharedMemorySize, GEMM_SMEM);
    cudaFuncSetAttribute(mma_gemm<3>, cudaFuncAttributeMaxDynamicSharedMemorySize, GEMM_SMEM);

    // prep
    split3_rows<<<(MROWS * DMODEL + 255) / 256, 256>>>(x, (__nv_bfloat16*)xp, MROWS, DMODEL);
    prep_qkvW<<<(1536 * DMODEL + 255) / 256, 256>>>(Wq, Wk, Wv);
    transpose_split3<<<(DMODEL * DMODEL + 255) / 256, 256>>>(Wo, (__nv_bfloat16*)wop, DMODEL, DMODEL);
    transpose_split3<<<(DMODEL * FFI + 255) / 256, 256>>>(W1, (__nv_bfloat16*)w1p, DMODEL, FFI);
    transpose_split3<<<(FFI * DMODEL + 255) / 256, 256>>>(W2, (__nv_bfloat16*)w2p, FFI, DMODEL);

    // 1. QKV: x' @ qkvW'^T -> scatter fp32 q/k/v   (M=8192, N=1536, Kp=1536)
    mma_gemm<0><<<dim3(1536 / 128, MROWS / 128), 256, GEMM_SMEM>>>(
        (const __nv_bfloat16*)xp, (const __nv_bfloat16*)qwp,
        nullptr, nullptr, nullptr, 1536, 1536);

    // 2. flash attention -> att' triple
    flash_attn<<<dim3(SEQ / 64, BATCH * NH), 256>>>();

    // 3. Wo: att' @ Wo'^T -> out' triple   (N=512, Kp=1536)
    mma_gemm<1><<<dim3(DMODEL / 128, MROWS / 128), 256, GEMM_SMEM>>>(
        (const __nv_bfloat16*)atp, (const __nv_bfloat16*)wop,
        nullptr, nullptr, (__nv_bfloat16*)outp, DMODEL, 1536);

    // 4. FFN1: relu(out' @ W1'^T + b1) -> h' triple   (N=2048, Kp=1536)
    mma_gemm<2><<<dim3(FFI / 128, MROWS / 128), 256, GEMM_SMEM>>>(
        (const __nv_bfloat16*)outp, (const __nv_bfloat16*)w1p,
        b1, nullptr, (__nv_bfloat16*)hp, FFI, 1536);

    // 5. FFN2: h' @ W2'^T + b2 -> y fp32   (N=512, Kp=6144)
    mma_gemm<3><<<dim3(DMODEL / 128, MROWS / 128), 256, GEMM_SMEM>>>(
        (const __nv_bfloat16*)hp, (const __nv_bfloat16*)w2p,
        b2, y, nullptr, DMODEL, 6144);
}

// round 4
// speedup vs baseline: 3.1880x; 1.9347x over previous
#include <cuda_runtime.h>
#include <cuda_bf16.h>
#include <math.h>
#include <stdint.h>

// ---------------------------------------------------------------------------
// Problem constants
// ---------------------------------------------------------------------------
constexpr int BATCH  = 4;
constexpr int SEQ    = 2048;
constexpr int DMODEL = 512;
constexpr int NH     = 8;
constexpr int HD     = 64;
constexpr int FFI    = 2048;
constexpr int MROWS  = BATCH * SEQ;   // 8192
constexpr int BH     = BATCH * NH;    // 32

// ---------------------------------------------------------------------------
// Baseline-PTX helpers (mma.sync / ldmatrix / cp.async only — no "a" features)
// ---------------------------------------------------------------------------
__device__ __forceinline__ uint32_t smem_u32(const void* p) {
    uint32_t a;
    asm("{ .reg .u64 t; cvta.to.shared.u64 t, %1; cvt.u32.u64 %0, t; }" : "=r"(a) : "l"(p));
    return a;
}
#define CP_ASYNC16(dst, src) \
    asm volatile("cp.async.cg.shared.global [%0], [%1], 16;" :: "r"(dst), "l"(src))
#define CP_COMMIT() asm volatile("cp.async.commit_group;" ::: "memory")
#define CP_WAIT(n)  asm volatile("cp.async.wait_group %0;" :: "n"(n) : "memory")

#define LDSM4(r0, r1, r2, r3, addr) \
    asm volatile("ldmatrix.sync.aligned.m8n8.x4.shared.b16 {%0,%1,%2,%3}, [%4];" \
        : "=r"(r0), "=r"(r1), "=r"(r2), "=r"(r3) : "r"(addr))
#define LDSM4T(r0, r1, r2, r3, addr) \
    asm volatile("ldmatrix.sync.aligned.m8n8.x4.trans.shared.b16 {%0,%1,%2,%3}, [%4];" \
        : "=r"(r0), "=r"(r1), "=r"(r2), "=r"(r3) : "r"(addr))

#define MMA16816(c, a, b0, b1) \
    asm volatile("mma.sync.aligned.m16n8k16.row.col.f32.bf16.bf16.f32 " \
        "{%0,%1,%2,%3}, {%4,%5,%6,%7}, {%8,%9}, {%0,%1,%2,%3};" \
        : "+f"((c)[0]), "+f"((c)[1]), "+f"((c)[2]), "+f"((c)[3]) \
        : "r"((a)[0]), "r"((a)[1]), "r"((a)[2]), "r"((a)[3]), "r"(b0), "r"(b1))

// ---------------------------------------------------------------------------
// Device scratch: A' = [hi | lo | hi], B' = [hi | hi | lo] along K (3x K)
// ---------------------------------------------------------------------------
#define AL __align__(16)
__device__ AL __nv_bfloat16 g_xp[MROWS * 3 * DMODEL];          // x'      [8192,1536]
__device__ AL __nv_bfloat16 g_qkvWp[1536 * 3 * DMODEL];        // B' qkv  [1536,1536]
__device__ AL __nv_bfloat16 g_qhi[BH * SEQ * HD], g_qlo[BH * SEQ * HD];
__device__ AL __nv_bfloat16 g_khi[BH * SEQ * HD], g_klo[BH * SEQ * HD];
__device__ AL __nv_bfloat16 g_vhi[BH * SEQ * HD], g_vlo[BH * SEQ * HD];
__device__ AL __nv_bfloat16 g_attp[MROWS * 3 * DMODEL];        // att'    [8192,1536]
__device__ AL __nv_bfloat16 g_WoTp[DMODEL * 3 * DMODEL];       // B' Wo   [512,1536]
__device__ AL __nv_bfloat16 g_outp[MROWS * 3 * DMODEL];        // out'    [8192,1536]
__device__ AL __nv_bfloat16 g_W1Tp[FFI * 3 * DMODEL];          // B' W1   [2048,1536]
__device__ AL __nv_bfloat16 g_hp[MROWS * 3 * FFI];             // h'      [8192,6144]
__device__ AL __nv_bfloat16 g_W2Tp[DMODEL * 3 * FFI];          // B' W2   [512,6144]

__device__ __forceinline__ void split2(float v, __nv_bfloat16& h, __nv_bfloat16& l) {
    h = __float2bfloat16_rn(v);
    l = __float2bfloat16_rn(v - __bfloat162float(h));
}
// pack (x, y) -> bf16x2 hi-pair and lo-pair (x in lower 16 bits)
__device__ __forceinline__ void pack_hl(float x, float y, uint32_t& hi, uint32_t& lo) {
    __nv_bfloat16 hx, lx, hy, ly;
    split2(x, hx, lx);
    split2(y, hy, ly);
    hi = ((uint32_t)__bfloat16_as_ushort(hy) << 16) | __bfloat16_as_ushort(hx);
    lo = ((uint32_t)__bfloat16_as_ushort(ly) << 16) | __bfloat16_as_ushort(lx);
}

// ---------------------------------------------------------------------------
// Prep kernels
// ---------------------------------------------------------------------------
__global__ void split3_rows(const float* __restrict__ in, __nv_bfloat16* __restrict__ out,
                            int M, int K) {
    int i = blockIdx.x * 256 + threadIdx.x;
    if (i >= M * K) return;
    int m = i / K, k = i - m * K;
    __nv_bfloat16 h, l; split2(in[i], h, l);
    size_t base = (size_t)m * 3 * K;
    out[base + k] = h; out[base + K + k] = l; out[base + 2 * K + k] = h;
}

__global__ void transpose_split3(const float* __restrict__ W, __nv_bfloat16* __restrict__ out,
                                 int Kd, int Nd) {
    int i = blockIdx.x * 256 + threadIdx.x;
    if (i >= Nd * Kd) return;
    int n = i / Kd, k = i - n * Kd;
    __nv_bfloat16 h, l; split2(W[(size_t)k * Nd + n], h, l);
    size_t base = (size_t)n * 3 * Kd;
    out[base + k] = h; out[base + Kd + k] = h; out[base + 2 * Kd + k] = l;
}

__global__ void prep_qkvW(const float* __restrict__ Wq, const float* __restrict__ Wk,
                          const float* __restrict__ Wv) {
    int i = blockIdx.x * 256 + threadIdx.x;
    if (i >= 1536 * DMODEL) return;
    int n = i >> 9, k = i & 511;
    int which = n >> 9, h = (n >> 6) & 7, kk = n & 63;
    const float* W = which == 0 ? Wq : which == 1 ? Wk : Wv;
    __nv_bfloat16 hh, ll; split2(W[((size_t)h * DMODEL + k) * HD + kk], hh, ll);
    size_t base = (size_t)n * 1536;
    g_qkvWp[base + k] = hh; g_qkvWp[base + 512 + k] = hh; g_qkvWp[base + 1024 + k] = ll;
}

// ---------------------------------------------------------------------------
// bf16 mma.sync GEMM (unchanged core from round 3)
// EPI: 0 = QKV scatter bf16 hi/lo, 1 = triple-split, 2 = bias+relu+triple, 3 = bias+fp32
// ---------------------------------------------------------------------------
constexpr int STAGE_B = 32768;
constexpr int GEMM_SMEM = 3 * STAGE_B;

template <int EPI>
__global__ __launch_bounds__(256, 2)
void mma_gemm(const __nv_bfloat16* __restrict__ A, const __nv_bfloat16* __restrict__ B,
              const float* __restrict__ bias, float* __restrict__ outF,
              __nv_bfloat16* __restrict__ outB, int N, int Kp) {
    extern __shared__ char smdyn[];
    const uint32_t sb = smem_u32(smdyn);
    const int tid = threadIdx.x, lane = tid & 31, wid = tid >> 5;
    const int wm = wid & 3, wn = wid >> 2;
    const int rowBase = blockIdx.y * 128, colBase = blockIdx.x * 128;
    const int chunks = Kp >> 6;

    float C[2][8][4];
#pragma unroll
    for (int a = 0; a < 2; a++)
#pragma unroll
        for (int b = 0; b < 8; b++)
#pragma unroll
            for (int c = 0; c < 4; c++) C[a][b][c] = 0.f;

    auto issue = [&](int cchunk) {
        int s = cchunk % 3;
        uint32_t stA = sb + s * STAGE_B, stB = stA + 16384;
        const char* Ag = (const char*)(A + (size_t)rowBase * Kp + cchunk * 64);
        const char* Bg = (const char*)(B + (size_t)colBase * Kp + cchunk * 64);
#pragma unroll
        for (int i = 0; i < 4; i++) {
            int id = tid + i * 256;
            int r = id >> 3, ch = id & 7;
            uint32_t off = (uint32_t)(r * 8 + (ch ^ (r & 7))) * 16;
            CP_ASYNC16(stA + off, Ag + (size_t)r * Kp * 2 + ch * 16);
            CP_ASYNC16(stB + off, Bg + (size_t)r * Kp * 2 + ch * 16);
        }
        CP_COMMIT();
    };

    issue(0);
    if (chunks > 1) issue(1);

    const int laneA_row = lane & 15;
    const int laneA_ks  = lane >> 4;
    const int laneB_row = (lane & 7) + ((lane >> 4) << 3);
    const int laneB_ks  = (lane >> 3) & 1;

    for (int c = 0; c < chunks; c++) {
        CP_WAIT(1);
        __syncthreads();
        if (c + 2 < chunks) issue(c + 2);

        int s = c % 3;
        uint32_t stA = sb + s * STAGE_B, stB = stA + 16384;

#pragma unroll
        for (int ks = 0; ks < 4; ks++) {
            uint32_t a[2][4];
#pragma unroll
            for (int mt = 0; mt < 2; mt++) {
                int rowA = wm * 32 + mt * 16 + laneA_row;
                int chA = ks * 2 + laneA_ks;
                uint32_t ad = stA + (uint32_t)(rowA * 8 + (chA ^ (rowA & 7))) * 16;
                LDSM4(a[mt][0], a[mt][1], a[mt][2], a[mt][3], ad);
            }
#pragma unroll
            for (int np = 0; np < 4; np++) {
                int rowB = wn * 64 + np * 16 + laneB_row;
                int chB = ks * 2 + laneB_ks;
                uint32_t bd = stB + (uint32_t)(rowB * 8 + (chB ^ (rowB & 7))) * 16;
                uint32_t b0, b1, b2, b3;
                LDSM4(b0, b1, b2, b3, bd);
#pragma unroll
                for (int mt = 0; mt < 2; mt++) {
                    MMA16816(C[mt][np * 2 + 0], a[mt], b0, b1);
                    MMA16816(C[mt][np * 2 + 1], a[mt], b2, b3);
                }
            }
        }
    }

#pragma unroll
    for (int mt = 0; mt < 2; mt++) {
#pragma unroll
        for (int half = 0; half < 2; half++) {
            int m = rowBase + wm * 32 + mt * 16 + (lane >> 2) + half * 8;
#pragma unroll
            for (int nt = 0; nt < 8; nt++) {
                int n = colBase + wn * 64 + nt * 8 + (lane & 3) * 2;
                float v0 = C[mt][nt][half * 2 + 0];
                float v1 = C[mt][nt][half * 2 + 1];
                if (EPI == 0) {
                    int b = m >> 11, t = m & 2047;
                    int which = n >> 9, h = (n >> 6) & 7, kk = n & 63;
                    __nv_bfloat16* dh = which == 0 ? g_qhi : which == 1 ? g_khi : g_vhi;
                    __nv_bfloat16* dl = which == 0 ? g_qlo : which == 1 ? g_klo : g_vlo;
                    uint32_t hi, lo;
                    pack_hl(v0, v1, hi, lo);
                    size_t idx = ((size_t)((b * NH + h) * SEQ + t)) * HD + kk;
                    *(uint32_t*)&dh[idx] = hi;
                    *(uint32_t*)&dl[idx] = lo;
                } else if (EPI == 3) {
                    float2 v = make_float2(v0 + bias[n], v1 + bias[n + 1]);
                    *(float2*)&outF[(size_t)m * N + n] = v;
                } else {
                    if (EPI == 2) {
                        v0 = fmaxf(v0 + bias[n], 0.f);
                        v1 = fmaxf(v1 + bias[n + 1], 0.f);
                    }
                    uint32_t hi, lo;
                    pack_hl(v0, v1, hi, lo);
                    size_t base = (size_t)m * (3 * N) + n;
                    *(uint32_t*)&outB[base]         = hi;
                    *(uint32_t*)&outB[base + N]     = lo;
                    *(uint32_t*)&outB[base + 2 * N] = hi;
                }
            }
        }
    }
}

// ---------------------------------------------------------------------------
// Flash attention via mma.sync bf16 (3-term split both matmuls).
// CTA: 128 queries x 8 warps (16 rows each), BN=64 keys/iter, 2-stage cp.async.
// smem: Qhi 16K | Qlo 16K | stage{0,1}: Khi 8K | Klo 8K | Vhi 8K | Vlo 8K
// ---------------------------------------------------------------------------
constexpr int F_STAGE = 32768;
constexpr int FLASH_SMEM = 32768 + 2 * F_STAGE;   // 96 KB

__global__ __launch_bounds__(256, 1)
void flash_mma() {
    extern __shared__ char smdyn[];
    const uint32_t sb = smem_u32(smdyn);
    const int tid = threadIdx.x, lane = tid & 31, wid = tid >> 5;
    const int bh = blockIdx.y;
    const int b = bh >> 3, h = bh & 7;
    const int q0 = blockIdx.x * 128;

    const uint32_t sQh = sb, sQl = sb + 16384;
    const size_t bhBase = (size_t)bh * SEQ * HD;

    auto issue_kv = [&](int t) {
        int s = t & 1;
        uint32_t st = sb + 32768 + s * F_STAGE;
        int key0 = t * 64;
        const __nv_bfloat16* srcs[4] = { g_khi, g_klo, g_vhi, g_vlo };
#pragma unroll
        for (int arr = 0; arr < 4; arr++) {
            uint32_t base = st + arr * 8192;
            const char* g = (const char*)(srcs[arr] + bhBase + (size_t)key0 * HD);
#pragma unroll
            for (int i = 0; i < 2; i++) {
                int id = tid + i * 256;       // 512 16B chunks
                int r = id >> 3, ch = id & 7;
                uint32_t off = (uint32_t)(r * 8 + (ch ^ (r & 7))) * 16;
                CP_ASYNC16(base + off, g + (size_t)r * 128 + ch * 16);
            }
        }
        CP_COMMIT();
    };

    issue_kv(0);
    issue_kv(1);

    // Q tiles (plain loads, swizzled store)
#pragma unroll
    for (int i = 0; i < 4; i++) {
        int id = tid + i * 256;               // 1024 chunks per array
        int r = id >> 3, ch = id & 7;
        uint32_t off = (uint32_t)(r * 8 + (ch ^ (r & 7))) * 16;
        size_t gidx = bhBase + (size_t)(q0 + r) * HD + ch * 8;
        *(float4*)(smdyn + (sQh - sb) + off) = *(const float4*)&g_qhi[gidx];
        *(float4*)(smdyn + (sQl - sb) + off) = *(const float4*)&g_qlo[gidx];
    }

    float o[8][4];
#pragma unroll
    for (int nt = 0; nt < 8; nt++)
#pragma unroll
        for (int j = 0; j < 4; j++) o[nt][j] = 0.f;
    float m0 = -1e30f, m1 = -1e30f, l0 = 0.f, l1 = 0.f;

    const int laneA_row = lane & 15;
    const int laneA_ks  = lane >> 4;
    const int laneB_row = (lane & 7) + ((lane >> 4) << 3);
    const int laneB_ks  = (lane >> 3) & 1;
    const int t4 = lane >> 3, rr = lane & 7;   // for trans V ldsm

    constexpr int NT = SEQ / 64;   // 32 key tiles
    for (int kt = 0; kt < NT; kt++) {
        if (kt < NT - 1) { CP_WAIT(1); } else { CP_WAIT(0); }
        __syncthreads();

        uint32_t st = sb + 32768 + (kt & 1) * F_STAGE;
        uint32_t sKh = st, sKl = st + 8192, sVh = st + 16384, sVl = st + 24576;

        // ---- S = Qh·Kh + Ql·Kh + Qh·Kl ----
        float c[8][4];
#pragma unroll
        for (int nt = 0; nt < 8; nt++)
#pragma unroll
            for (int j = 0; j < 4; j++) c[nt][j] = 0.f;

#pragma unroll
        for (int ks = 0; ks < 4; ks++) {
            uint32_t ah[4], al[4];
            {
                int rowA = wid * 16 + laneA_row;
                int chA = ks * 2 + laneA_ks;
                uint32_t sw = (uint32_t)(rowA * 8 + (chA ^ (rowA & 7))) * 16;
                LDSM4(ah[0], ah[1], ah[2], ah[3], sQh + sw);
                LDSM4(al[0], al[1], al[2], al[3], sQl + sw);
            }
#pragma unroll
            for (int np = 0; np < 4; np++) {
                int rowB = np * 16 + laneB_row;
                int chB = ks * 2 + laneB_ks;
                uint32_t sw = (uint32_t)(rowB * 8 + (chB ^ (rowB & 7))) * 16;
                uint32_t kh0, kh1, kh2, kh3, kl0, kl1, kl2, kl3;
                LDSM4(kh0, kh1, kh2, kh3, sKh + sw);
                LDSM4(kl0, kl1, kl2, kl3, sKl + sw);
                MMA16816(c[np * 2 + 0], ah, kh0, kh1);
                MMA16816(c[np * 2 + 0], al, kh0, kh1);
                MMA16816(c[np * 2 + 0], ah, kl0, kl1);
                MMA16816(c[np * 2 + 1], ah, kh2, kh3);
                MMA16816(c[np * 2 + 1], al, kh2, kh3);
                MMA16816(c[np * 2 + 1], ah, kl2, kl3);
            }
        }

        // ---- online softmax (rows: r0=lane>>2, r1=r0+8 within warp tile) ----
        float mx0 = -1e30f, mx1 = -1e30f;
#pragma unroll
        for (int nt = 0; nt < 8; nt++) {
            c[nt][0] *= 0.125f; c[nt][1] *= 0.125f;
            c[nt][2] *= 0.125f; c[nt][3] *= 0.125f;
            mx0 = fmaxf(mx0, fmaxf(c[nt][0], c[nt][1]));
            mx1 = fmaxf(mx1, fmaxf(c[nt][2], c[nt][3]));
        }
        mx0 = fmaxf(mx0, __shfl_xor_sync(0xffffffffu, mx0, 1));
        mx0 = fmaxf(mx0, __shfl_xor_sync(0xffffffffu, mx0, 2));
        mx1 = fmaxf(mx1, __shfl_xor_sync(0xffffffffu, mx1, 1));
        mx1 = fmaxf(mx1, __shfl_xor_sync(0xffffffffu, mx1, 2));

        float mn0 = fmaxf(m0, mx0), mn1 = fmaxf(m1, mx1);
        float a0 = __expf(m0 - mn0), a1 = __expf(m1 - mn1);
        m0 = mn0; m1 = mn1;

        float s0 = 0.f, s1 = 0.f;
#pragma unroll
        for (int nt = 0; nt < 8; nt++) {
            c[nt][0] = __expf(c[nt][0] - m0);
            c[nt][1] = __expf(c[nt][1] - m0);
            c[nt][2] = __expf(c[nt][2] - m1);
            c[nt][3] = __expf(c[nt][3] - m1);
            s0 += c[nt][0] + c[nt][1];
            s1 += c[nt][2] + c[nt][3];
        }
        s0 += __shfl_xor_sync(0xffffffffu, s0, 1);
        s0 += __shfl_xor_sync(0xffffffffu, s0, 2);
        s1 += __shfl_xor_sync(0xffffffffu, s1, 1);
        s1 += __shfl_xor_sync(0xffffffffu, s1, 2);
        l0 = l0 * a0 + s0;
        l1 = l1 * a1 + s1;

#pragma unroll
        for (int nt = 0; nt < 8; nt++) {
            o[nt][0] *= a0; o[nt][1] *= a0;
            o[nt][2] *= a1; o[nt][3] *= a1;
        }

        // ---- P -> bf16 hi/lo A-fragments ----
        uint32_t ph[4][4], pl[4][4];
#pragma unroll
        for (int pk = 0; pk < 4; pk++) {
            int n0 = pk * 2, n1 = pk * 2 + 1;
            pack_hl(c[n0][0], c[n0][1], ph[pk][0], pl[pk][0]);
            pack_hl(c[n0][2], c[n0][3], ph[pk][1], pl[pk][1]);
            pack_hl(c[n1][0], c[n1][1], ph[pk][2], pl[pk][2]);
            pack_hl(c[n1][2], c[n1][3], ph[pk][3], pl[pk][3]);
        }

        // ---- O += Ph·Vh + Pl·Vh + Ph·Vl ----
#pragma unroll
        for (int pk = 0; pk < 4; pk++) {
#pragma unroll
            for (int np = 0; np < 4; np++) {
                int rowV = pk * 16 + (t4 & 1) * 8 + rr;
                int chV = np * 2 + (t4 >> 1);
                uint32_t sw = (uint32_t)(rowV * 8 + (chV ^ (rowV & 7))) * 16;
                uint32_t vh0, vh1, vh2, vh3, vl0, vl1, vl2, vl3;
                LDSM4T(vh0, vh1, vh2, vh3, sVh + sw);
                LDSM4T(vl0, vl1, vl2, vl3, sVl + sw);
                MMA16816(o[np * 2 + 0], ph[pk], vh0, vh1);
                MMA16816(o[np * 2 + 0], pl[pk], vh0, vh1);
                MMA16816(o[np * 2 + 0], ph[pk], vl0, vl1);
                MMA16816(o[np * 2 + 1], ph[pk], vh2, vh3);
                MMA16816(o[np * 2 + 1], pl[pk], vh2, vh3);
                MMA16816(o[np * 2 + 1], ph[pk], vl2, vl3);
            }
        }

        __syncthreads();                 // done reading stage before overwrite
        if (kt + 2 < NT) issue_kv(kt + 2);
    }

    // ---- epilogue: write att' triple in raw-reshape layout ----
    float inv0 = 1.f / l0, inv1 = 1.f / l1;
#pragma unroll
    for (int half = 0; half < 2; half++) {
        int t = q0 + wid * 16 + (lane >> 2) + half * 8;
        float inv = half ? inv1 : inv0;
        size_t row2 = (size_t)b * SEQ + h * 256 + (t >> 3);
        size_t rb = row2 * 1536 + (t & 7) * 64;
#pragma unroll
        for (int nt = 0; nt < 8; nt++) {
            int col = nt * 8 + (lane & 3) * 2;
            float v0 = o[nt][half * 2 + 0] * inv;
            float v1 = o[nt][half * 2 + 1] * inv;
            uint32_t hi, lo;
            pack_hl(v0, v1, hi, lo);
            *(uint32_t*)&g_attp[rb + col]        = hi;
            *(uint32_t*)&g_attp[rb + 512 + col]  = lo;
            *(uint32_t*)&g_attp[rb + 1024 + col] = hi;
        }
    }
}

// ---------------------------------------------------------------------------
// Launch
// ---------------------------------------------------------------------------
extern "C" void kernel_launch(void* const* d_in, const int* in_sizes, int n_in,
                              void* d_out, int out_size) {
    const float* x  = (const float*)d_in[0];
    const float* Wq = (const float*)d_in[1];
    const float* Wk = (const float*)d_in[2];
    const float* Wv = (const float*)d_in[3];
    const float* Wo = (const float*)d_in[4];
    const float* W1 = (const float*)d_in[5];
    const float* b1 = (const float*)d_in[6];
    const float* W2 = (const float*)d_in[7];
    const float* b2 = (const float*)d_in[8];
    float* y = (float*)d_out;

    void *xp, *qwp, *atp, *wop, *outp, *w1p, *hp, *w2p;
    cudaGetSymbolAddress(&xp,  g_xp);
    cudaGetSymbolAddress(&qwp, g_qkvWp);
    cudaGetSymbolAddress(&atp, g_attp);
    cudaGetSymbolAddress(&wop, g_WoTp);
    cudaGetSymbolAddress(&outp, g_outp);
    cudaGetSymbolAddress(&w1p, g_W1Tp);
    cudaGetSymbolAddress(&hp,  g_hp);
    cudaGetSymbolAddress(&w2p, g_W2Tp);

    cudaFuncSetAttribute(mma_gemm<0>, cudaFuncAttributeMaxDynamicSharedMemorySize, GEMM_SMEM);
    cudaFuncSetAttribute(mma_gemm<1>, cudaFuncAttributeMaxDynamicSharedMemorySize, GEMM_SMEM);
    cudaFuncSetAttribute(mma_gemm<2>, cudaFuncAttributeMaxDynamicSharedMemorySize, GEMM_SMEM);
    cudaFuncSetAttribute(mma_gemm<3>, cudaFuncAttributeMaxDynamicSharedMemorySize, GEMM_SMEM);
    cudaFuncSetAttribute(flash_mma, cudaFuncAttributeMaxDynamicSharedMemorySize, FLASH_SMEM);

    // prep
    split3_rows<<<(MROWS * DMODEL + 255) / 256, 256>>>(x, (__nv_bfloat16*)xp, MROWS, DMODEL);
    prep_qkvW<<<(1536 * DMODEL + 255) / 256, 256>>>(Wq, Wk, Wv);
    transpose_split3<<<(DMODEL * DMODEL + 255) / 256, 256>>>(Wo, (__nv_bfloat16*)wop, DMODEL, DMODEL);
    transpose_split3<<<(DMODEL * FFI + 255) / 256, 256>>>(W1, (__nv_bfloat16*)w1p, DMODEL, FFI);
    transpose_split3<<<(FFI * DMODEL + 255) / 256, 256>>>(W2, (__nv_bfloat16*)w2p, FFI, DMODEL);

    // 1. QKV: x' @ qkvW'^T -> q/k/v bf16 hi/lo
    mma_gemm<0><<<dim3(1536 / 128, MROWS / 128), 256, GEMM_SMEM>>>(
        (const __nv_bfloat16*)xp, (const __nv_bfloat16*)qwp,
        nullptr, nullptr, nullptr, 1536, 1536);

    // 2. flash attention (mma.sync) -> att' triple
    flash_mma<<<dim3(SEQ / 128, BH), 256, FLASH_SMEM>>>();

    // 3. Wo: att' @ Wo'^T -> out' triple
    mma_gemm<1><<<dim3(DMODEL / 128, MROWS / 128), 256, GEMM_SMEM>>>(
        (const __nv_bfloat16*)atp, (const __nv_bfloat16*)wop,
        nullptr, nullptr, (__nv_bfloat16*)outp, DMODEL, 1536);

    // 4. FFN1: relu(out' @ W1'^T + b1) -> h' triple
    mma_gemm<2><<<dim3(FFI / 128, MROWS / 128), 256, GEMM_SMEM>>>(
        (const __nv_bfloat16*)outp, (const __nv_bfloat16*)w1p,
        b1, nullptr, (__nv_bfloat16*)hp, FFI, 1536);

    // 5. FFN2: h' @ W2'^T + b2 -> y fp32
    mma_gemm<3><<<dim3(DMODEL / 128, MROWS / 128), 256, GEMM_SMEM>>>(
        (const __nv_bfloat16*)hp, (const __nv_bfloat16*)w2p,
        b2, y, nullptr, DMODEL, 6144);
}